// round 4
// baseline (speedup 1.0000x reference)
#include <cuda_runtime.h>
#include <cuda_bf16.h>
#include <cuda_fp16.h>

// Problem constants (fixed by the dataset)
#define NN 100000
#define EE 1600000
#define HH 32
#define NTILE 98                       // ceil(NN / 1024)

#define CDIV(a, b) (((a) + (b) - 1) / (b))

// Scratch (static device globals; no allocation allowed)
__device__ int      g_deg[NN];         // zeroed by previous call's scan3 (init: static zero)
__device__ int      g_rowptr[NN + 1];
__device__ int      g_cursor[NN];
__device__ int      g_blocksums[NTILE];
__device__ float    g_dinv[NN];
__device__ int      g_csri[EE];        // src indices, bucketed by dst
__device__ float    g_h0[NN * HH];     // ping
__device__ float    g_h1[NN * HH];     // pong
__device__ __half   g_t[NN * HH];      // t'[i] = (relu(h[i]) @ W) * dinv[i], fp16
__device__ unsigned g_bar_arrive;      // grid barrier state
__device__ unsigned g_bar_gen;

// ---------------------------------------------------------------------------
// Software grid barrier (all blocks resident by construction).
// ---------------------------------------------------------------------------
__device__ __forceinline__ void gsync() {
    __threadfence();
    __syncthreads();
    if (threadIdx.x == 0) {
        unsigned gen = *(volatile unsigned*)&g_bar_gen;
        unsigned rank = atomicAdd(&g_bar_arrive, 1u);
        if (rank == gridDim.x - 1) {
            g_bar_arrive = 0;
            __threadfence();
            atomicExch(&g_bar_gen, gen + 1u);
        } else {
            while (*(volatile unsigned*)&g_bar_gen == gen) { __nanosleep(64); }
        }
    }
    __syncthreads();
    __threadfence();
}

__device__ __forceinline__ float4 unpk(uint2 u) {
    __half2 a = *(__half2*)&u.x;
    __half2 b = *(__half2*)&u.y;
    float2 fa = __half22float2(a), fb = __half22float2(b);
    return make_float4(fa.x, fa.y, fb.x, fb.y);
}

// ---------------------------------------------------------------------------
// Dense transform: t'[i] = (relu(hin[i]) @ W) * dinv[i], stored fp16.
// ---------------------------------------------------------------------------
__device__ __forceinline__ void xform_phase(const float* __restrict__ hin,
                                            const float* __restrict__ W, float* sW) {
    for (int i = threadIdx.x; i < 1024; i += blockDim.x) sW[i] = W[i];
    __syncthreads();
    int stride = gridDim.x * blockDim.x;
    for (int i = blockIdx.x * blockDim.x + threadIdx.x; i < NN; i += stride) {
        float acc[32];
#pragma unroll
        for (int j = 0; j < 32; j++) acc[j] = 0.0f;
        const float4* hp = (const float4*)(hin + i * HH);
#pragma unroll
        for (int q = 0; q < 8; q++) {
            float4 v4 = hp[q];
            float vv[4] = {fmaxf(v4.x, 0.0f), fmaxf(v4.y, 0.0f),
                           fmaxf(v4.z, 0.0f), fmaxf(v4.w, 0.0f)};
#pragma unroll
            for (int r = 0; r < 4; r++) {
                float v = vv[r];
                int k = 4 * q + r;
#pragma unroll
                for (int j = 0; j < 32; j++) acc[j] += v * sW[k * 32 + j];
            }
        }
        float di = g_dinv[i];
        __half2* tp = (__half2*)&g_t[i * HH];
#pragma unroll
        for (int q = 0; q < 16; q++)
            tp[q] = __float22half2_rn(make_float2(acc[2 * q] * di, acc[2 * q + 1] * di));
    }
}

// ---------------------------------------------------------------------------
// 8-lane-per-node gather (no atomics):
//   hout[i] = b + dinv[i] * ( t'[i] + sum_{e in in(i)} t'[src(e)] )
// Each lane owns 4 columns (uint2 = 4 halves). Per edge: 4B bcast + 64B row.
// ---------------------------------------------------------------------------
__device__ __forceinline__ void gather_phase(float* __restrict__ hout,
                                             const float* __restrict__ b) {
    int stride = gridDim.x * blockDim.x;
    const uint2* tp = (const uint2*)g_t;
    for (int g = blockIdx.x * blockDim.x + threadIdx.x; g < NN * 8; g += stride) {
        int node = g >> 3, sub = g & 7;
        float4 acc = unpk(__ldg(tp + node * 8 + sub));   // self term
        float4 acc2 = make_float4(0.0f, 0.0f, 0.0f, 0.0f);
        int e = g_rowptr[node];
        int e1 = g_rowptr[node + 1];
        for (; e + 1 < e1; e += 2) {
            int s0 = __ldg(&g_csri[e]);
            int s1 = __ldg(&g_csri[e + 1]);
            float4 v0 = unpk(__ldg(tp + s0 * 8 + sub));
            float4 v1 = unpk(__ldg(tp + s1 * 8 + sub));
            acc.x += v0.x; acc.y += v0.y; acc.z += v0.z; acc.w += v0.w;
            acc2.x += v1.x; acc2.y += v1.y; acc2.z += v1.z; acc2.w += v1.w;
        }
        if (e < e1) {
            float4 v0 = unpk(__ldg(tp + __ldg(&g_csri[e]) * 8 + sub));
            acc.x += v0.x; acc.y += v0.y; acc.z += v0.z; acc.w += v0.w;
        }
        float di = g_dinv[node];
        float4 bb = __ldg((const float4*)b + sub);
        float4 o = make_float4(bb.x + di * (acc.x + acc2.x),
                               bb.y + di * (acc.y + acc2.y),
                               bb.z + di * (acc.z + acc2.z),
                               bb.w + di * (acc.w + acc2.w));
        ((float4*)hout)[node * 8 + sub] = o;
    }
}

// ---------------------------------------------------------------------------
// The whole network as one persistent kernel.
// ---------------------------------------------------------------------------
__global__ void __launch_bounds__(256, 4) fused_kernel(
    const float* __restrict__ x, const float* __restrict__ y,
    const int* __restrict__ src, const int* __restrict__ dst,
    const int* __restrict__ bidx, const int* __restrict__ iidx, int NB,
    const float* __restrict__ Wb1, const float* __restrict__ bb1,
    const float* __restrict__ Wb2, const float* __restrict__ bb2,
    const float* __restrict__ Wi1, const float* __restrict__ bi1,
    const float* __restrict__ Wi2, const float* __restrict__ bi2,
    const float* __restrict__ Wc1, const float* __restrict__ bc1,
    const float* __restrict__ Wc2, const float* __restrict__ bc2,
    const float* __restrict__ Wc3, const float* __restrict__ bc3,
    const float* __restrict__ Wf, const float* __restrict__ bf,
    float* __restrict__ out) {
    __shared__ float smem[2336];
    int* sInt = (int*)smem;
    int tid = threadIdx.x;
    int gid = blockIdx.x * blockDim.x + tid;
    int stride = gridDim.x * blockDim.x;

    // ===== Phase A: encoders (per node) + degree count (per edge) =====
    // smem layout: [0:96) Wb1 | [96:128) bb1 | [128:1152) Wb2 | [1152:1184) bb2
    //              [1184:1248) Wi1 | [1248:1280) bi1 | [1280:2304) Wi2 | [2304:2336) bi2
    for (int i = tid; i < 96; i += 256) smem[i] = Wb1[i];
    for (int i = tid; i < 64; i += 256) smem[1184 + i] = Wi1[i];
    for (int i = tid; i < 32; i += 256) {
        smem[96 + i] = bb1[i];   smem[1152 + i] = bb2[i];
        smem[1248 + i] = bi1[i]; smem[2304 + i] = bi2[i];
    }
    for (int i = tid; i < 1024; i += 256) {
        smem[128 + i] = Wb2[i];
        smem[1280 + i] = Wi2[i];
    }
    __syncthreads();

    for (int j = gid; j < NN; j += stride) {
        bool bd = j < NB;
        int node = bd ? __ldg(&bidx[j]) : __ldg(&iidx[j - NB]);
        const float* W1 = bd ? smem : smem + 1184;
        const float* b1 = bd ? smem + 96 : smem + 1248;
        const float* W2 = bd ? smem + 128 : smem + 1280;
        const float* b2 = bd ? smem + 1152 : smem + 2304;
        float2 xv = __ldg((const float2*)x + node);
        float yv = bd ? __ldg(&y[node]) : 0.0f;

        float acc[32];
#pragma unroll
        for (int jj = 0; jj < 32; jj++) acc[jj] = b2[jj];
#pragma unroll
        for (int k = 0; k < 32; k++) {
            float a = xv.x * W1[k] + xv.y * W1[32 + k] + b1[k];
            if (bd) a += yv * W1[64 + k];
            a = fmaxf(a, 0.0f);
#pragma unroll
            for (int jj = 0; jj < 32; jj++) acc[jj] += a * W2[k * 32 + jj];
        }
        float4* hp = (float4*)&g_h0[node * HH];
#pragma unroll
        for (int q = 0; q < 8; q++)
            hp[q] = make_float4(fmaxf(acc[4 * q + 0], 0.0f), fmaxf(acc[4 * q + 1], 0.0f),
                                fmaxf(acc[4 * q + 2], 0.0f), fmaxf(acc[4 * q + 3], 0.0f));
    }
    for (int e = gid; e < EE; e += stride) atomicAdd(&g_deg[__ldg(&dst[e])], 1);
    gsync();

    // ===== Phase B: dinv + tile-local exclusive scans =====
    for (int i = gid; i < NN; i += stride)
        g_dinv[i] = rsqrtf((float)(g_deg[i] + 1));
    for (int tile = blockIdx.x; tile < NTILE; tile += gridDim.x) {
        __syncthreads();
        int base = tile * 1024 + tid * 4;
        int v[4];
#pragma unroll
        for (int r = 0; r < 4; r++) v[r] = (base + r < NN) ? g_deg[base + r] : 0;
        int ts = v[0] + v[1] + v[2] + v[3];
        sInt[tid] = ts;
        __syncthreads();
#pragma unroll
        for (int d = 1; d < 256; d <<= 1) {
            int t2 = (tid >= d) ? sInt[tid - d] : 0;
            __syncthreads();
            sInt[tid] += t2;
            __syncthreads();
        }
        int run = sInt[tid] - ts;   // exclusive prefix of this thread's chunk
#pragma unroll
        for (int r = 0; r < 4; r++) {
            if (base + r < NN) g_rowptr[base + r] = run;
            run += v[r];
        }
        if (tid == 255) g_blocksums[tile] = sInt[255];
    }
    gsync();

    // ===== Phase C: scan of tile sums (block 0 only) =====
    if (blockIdx.x == 0) {
        int v = (tid < NTILE) ? g_blocksums[tid] : 0;
        sInt[tid] = v;
        __syncthreads();
#pragma unroll
        for (int d = 1; d < 256; d <<= 1) {
            int t2 = (tid >= d) ? sInt[tid - d] : 0;
            __syncthreads();
            sInt[tid] += t2;
            __syncthreads();
        }
        if (tid < NTILE) g_blocksums[tid] = sInt[tid] - v;  // exclusive
    }
    gsync();

    // ===== Phase D: finalize rowptr, cursor; reset deg for next call =====
    for (int i = gid; i < NN; i += stride) {
        int r = g_rowptr[i] + g_blocksums[i >> 10];
        g_rowptr[i] = r;
        g_cursor[i] = r;
        g_deg[i] = 0;
    }
    if (gid == 0) g_rowptr[NN] = EE;
    gsync();

    // ===== Phase E: CSR bucket fill =====
    for (int e = gid; e < EE; e += stride) {
        int s = __ldg(&src[e]);
        int d = __ldg(&dst[e]);
        int pos = atomicAdd(&g_cursor[d], 1);
        g_csri[pos] = s;
    }
    gsync();

    // ===== Convs =====
    xform_phase(g_h0, Wc1, smem); gsync();
    gather_phase(g_h1, bc1);      gsync();
    xform_phase(g_h1, Wc2, smem); gsync();
    gather_phase(g_h0, bc2);      gsync();
    xform_phase(g_h0, Wc3, smem); gsync();
    gather_phase(g_h1, bc3);      gsync();

    // ===== Head: out[i] = dot(relu(h1[i]), Wf) + bf =====
    if (tid < 32) smem[tid] = Wf[tid];
    if (tid == 32) smem[32] = bf[0];
    __syncthreads();
    for (int i = gid; i < NN; i += stride) {
        const float4* hp = (const float4*)(g_h1 + i * HH);
        float acc = smem[32];
#pragma unroll
        for (int q = 0; q < 8; q++) {
            float4 v = hp[q];
            acc += fmaxf(v.x, 0.0f) * smem[4 * q + 0];
            acc += fmaxf(v.y, 0.0f) * smem[4 * q + 1];
            acc += fmaxf(v.z, 0.0f) * smem[4 * q + 2];
            acc += fmaxf(v.w, 0.0f) * smem[4 * q + 3];
        }
        out[i] = acc;
    }
}

extern "C" void kernel_launch(void* const* d_in, const int* in_sizes, int n_in,
                              void* d_out, int out_size) {
    const float* x    = (const float*)d_in[0];
    const float* y    = (const float*)d_in[1];
    const int*   ei   = (const int*)d_in[2];
    const int*   bidx = (const int*)d_in[3];
    const int*   iidx = (const int*)d_in[4];
    const float* Wb1 = (const float*)d_in[5];
    const float* bb1 = (const float*)d_in[6];
    const float* Wb2 = (const float*)d_in[7];
    const float* bb2 = (const float*)d_in[8];
    const float* Wi1 = (const float*)d_in[9];
    const float* bi1 = (const float*)d_in[10];
    const float* Wi2 = (const float*)d_in[11];
    const float* bi2 = (const float*)d_in[12];
    const float* Wc1 = (const float*)d_in[13];
    const float* bc1 = (const float*)d_in[14];
    const float* Wc2 = (const float*)d_in[15];
    const float* bc2 = (const float*)d_in[16];
    const float* Wc3 = (const float*)d_in[17];
    const float* bc3 = (const float*)d_in[18];
    const float* Wf  = (const float*)d_in[19];
    const float* bf  = (const float*)d_in[20];

    int NB = in_sizes[3];
    const int* src = ei;        // edge_index[0,:]
    const int* dst = ei + EE;   // edge_index[1,:]

    // Exactly-resident grid for the software grid barrier.
    int dev = 0;
    cudaGetDevice(&dev);
    int sms = 148;
    cudaDeviceGetAttribute(&sms, cudaDevAttrMultiProcessorCount, dev);
    int per = 1;
    cudaOccupancyMaxActiveBlocksPerMultiprocessor(&per, fused_kernel, 256, 0);
    if (per < 1) per = 1;
    int nblk = sms * per;

    fused_kernel<<<nblk, 256>>>(x, y, src, dst, bidx, iidx, NB,
                                Wb1, bb1, Wb2, bb2, Wi1, bi1, Wi2, bi2,
                                Wc1, bc1, Wc2, bc2, Wc3, bc3, Wf, bf,
                                (float*)d_out);
}

// round 6
// speedup vs baseline: 1.0849x; 1.0849x over previous
#include <cuda_runtime.h>
#include <cuda_bf16.h>
#include <cuda_fp16.h>

// Problem constants (fixed by the dataset)
#define NN 100000
#define EE 1600000
#define HH 32
#define NTILE 98                       // ceil(NN / 1024)

#define CDIV(a, b) (((a) + (b) - 1) / (b))

// Scratch (static device globals; no allocation allowed)
__device__ int      g_deg[NN];         // zeroed by this kernel each call (phase D)
__device__ int      g_rowptr[NN + 1];
__device__ int      g_cursor[NN];
__device__ int      g_blocksums[NTILE];
__device__ float    g_dinv[NN];
__device__ int      g_csri[EE];        // src indices, bucketed by dst
__device__ float    g_h0[NN * HH];     // ping
__device__ float    g_h1[NN * HH];     // pong
__device__ __half   g_t[NN * HH];      // t'[i] = (relu(h[i]) @ W) * dinv[i], fp16
__device__ unsigned g_bar_arrive;      // grid barrier state
__device__ unsigned g_bar_gen;

// ---------------------------------------------------------------------------
// Software grid barrier (all blocks resident by construction).
// ---------------------------------------------------------------------------
__device__ __forceinline__ void gsync() {
    __threadfence();
    __syncthreads();
    if (threadIdx.x == 0) {
        unsigned gen = *(volatile unsigned*)&g_bar_gen;
        unsigned rank = atomicAdd(&g_bar_arrive, 1u);
        if (rank == gridDim.x - 1) {
            g_bar_arrive = 0;
            __threadfence();
            atomicExch(&g_bar_gen, gen + 1u);
        } else {
            while (*(volatile unsigned*)&g_bar_gen == gen) { __nanosleep(64); }
        }
    }
    __syncthreads();
    __threadfence();
}

__device__ __forceinline__ float4 unpk(uint2 u) {
    __half2 a = *(__half2*)&u.x;
    __half2 b = *(__half2*)&u.y;
    float2 fa = __half22float2(a), fb = __half22float2(b);
    return make_float4(fa.x, fa.y, fb.x, fb.y);
}

// ---------------------------------------------------------------------------
// Dense transform: t'[i] = (relu(hin[i]) @ W) * dinv[i], stored fp16.
// Output tiled in chunks of 8 columns (acc[8]) to keep registers low; the
// 128B input row is re-read per tile from L1 (hit).
// ---------------------------------------------------------------------------
__device__ __forceinline__ void xform_phase(const float* __restrict__ hin,
                                            const float* __restrict__ W, float* sW) {
    for (int i = threadIdx.x; i < 1024; i += blockDim.x) sW[i] = W[i];
    __syncthreads();
    int stride = gridDim.x * blockDim.x;
    for (int i = blockIdx.x * blockDim.x + threadIdx.x; i < NN; i += stride) {
        const float4* hp = (const float4*)(hin + i * HH);
        float di = g_dinv[i];
        __half2* tp = (__half2*)&g_t[i * HH];
#pragma unroll
        for (int tile = 0; tile < 4; tile++) {
            float acc[8];
#pragma unroll
            for (int j = 0; j < 8; j++) acc[j] = 0.0f;
#pragma unroll
            for (int q = 0; q < 8; q++) {
                float4 v4 = hp[q];
                float vv[4] = {fmaxf(v4.x, 0.0f), fmaxf(v4.y, 0.0f),
                               fmaxf(v4.z, 0.0f), fmaxf(v4.w, 0.0f)};
#pragma unroll
                for (int r = 0; r < 4; r++) {
                    float v = vv[r];
                    const float* wrow = sW + (4 * q + r) * 32 + tile * 8;
#pragma unroll
                    for (int j = 0; j < 8; j++) acc[j] += v * wrow[j];
                }
            }
#pragma unroll
            for (int q = 0; q < 4; q++)
                tp[tile * 4 + q] =
                    __float22half2_rn(make_float2(acc[2 * q] * di, acc[2 * q + 1] * di));
        }
    }
}

// ---------------------------------------------------------------------------
// 8-lane-per-node gather (no atomics):
//   hout[i] = b + dinv[i] * ( t'[i] + sum_{e in in(i)} t'[src(e)] )
// Each lane owns 4 columns (uint2 = 4 halves). Per edge: 4B bcast + 64B row.
// ---------------------------------------------------------------------------
__device__ __forceinline__ void gather_phase(float* __restrict__ hout,
                                             const float* __restrict__ b) {
    int stride = gridDim.x * blockDim.x;
    const uint2* tp = (const uint2*)g_t;
    for (int g = blockIdx.x * blockDim.x + threadIdx.x; g < NN * 8; g += stride) {
        int node = g >> 3, sub = g & 7;
        float4 acc = unpk(__ldg(tp + node * 8 + sub));   // self term
        float4 acc2 = make_float4(0.0f, 0.0f, 0.0f, 0.0f);
        int e = __ldg(&g_rowptr[node]);
        int e1 = __ldg(&g_rowptr[node + 1]);
        for (; e + 1 < e1; e += 2) {
            int s0 = __ldg(&g_csri[e]);
            int s1 = __ldg(&g_csri[e + 1]);
            float4 v0 = unpk(__ldg(tp + s0 * 8 + sub));
            float4 v1 = unpk(__ldg(tp + s1 * 8 + sub));
            acc.x += v0.x; acc.y += v0.y; acc.z += v0.z; acc.w += v0.w;
            acc2.x += v1.x; acc2.y += v1.y; acc2.z += v1.z; acc2.w += v1.w;
        }
        if (e < e1) {
            float4 v0 = unpk(__ldg(tp + __ldg(&g_csri[e]) * 8 + sub));
            acc.x += v0.x; acc.y += v0.y; acc.z += v0.z; acc.w += v0.w;
        }
        float di = g_dinv[node];
        float4 bb = __ldg((const float4*)b + sub);
        float4 o = make_float4(bb.x + di * (acc.x + acc2.x),
                               bb.y + di * (acc.y + acc2.y),
                               bb.z + di * (acc.z + acc2.z),
                               bb.w + di * (acc.w + acc2.w));
        ((float4*)hout)[node * 8 + sub] = o;
    }
}

// ---------------------------------------------------------------------------
// The whole network as one persistent kernel.
// ---------------------------------------------------------------------------
__global__ void __launch_bounds__(256, 3) fused_kernel(
    const float* __restrict__ x, const float* __restrict__ y,
    const int* __restrict__ src, const int* __restrict__ dst,
    const int* __restrict__ bidx, const int* __restrict__ iidx, int NB,
    const float* __restrict__ Wb1, const float* __restrict__ bb1,
    const float* __restrict__ Wb2, const float* __restrict__ bb2,
    const float* __restrict__ Wi1, const float* __restrict__ bi1,
    const float* __restrict__ Wi2, const float* __restrict__ bi2,
    const float* __restrict__ Wc1, const float* __restrict__ bc1,
    const float* __restrict__ Wc2, const float* __restrict__ bc2,
    const float* __restrict__ Wc3, const float* __restrict__ bc3,
    const float* __restrict__ Wf, const float* __restrict__ bf,
    float* __restrict__ out) {
    __shared__ float smem[2336];
    int* sInt = (int*)smem;
    int tid = threadIdx.x;
    int gid = blockIdx.x * blockDim.x + tid;
    int stride = gridDim.x * blockDim.x;

    // ===== Phase A: encoders (per node) + degree count (per edge) =====
    // smem layout: [0:96) Wb1 | [96:128) bb1 | [128:1152) Wb2 | [1152:1184) bb2
    //              [1184:1248) Wi1 | [1248:1280) bi1 | [1280:2304) Wi2 | [2304:2336) bi2
    for (int i = tid; i < 96; i += 256) smem[i] = Wb1[i];
    for (int i = tid; i < 64; i += 256) smem[1184 + i] = Wi1[i];
    for (int i = tid; i < 32; i += 256) {
        smem[96 + i] = bb1[i];   smem[1152 + i] = bb2[i];
        smem[1248 + i] = bi1[i]; smem[2304 + i] = bi2[i];
    }
    for (int i = tid; i < 1024; i += 256) {
        smem[128 + i] = Wb2[i];
        smem[1280 + i] = Wi2[i];
    }
    __syncthreads();

    for (int j = gid; j < NN; j += stride) {
        bool bd = j < NB;
        int node = bd ? __ldg(&bidx[j]) : __ldg(&iidx[j - NB]);
        const float* W1 = bd ? smem : smem + 1184;
        const float* b1 = bd ? smem + 96 : smem + 1248;
        const float* W2 = bd ? smem + 128 : smem + 1280;
        const float* b2 = bd ? smem + 1152 : smem + 2304;
        float2 xv = __ldg((const float2*)x + node);
        float yv = bd ? __ldg(&y[node]) : 0.0f;

        float4* hp = (float4*)&g_h0[node * HH];
        // Output tiled in chunks of 8; hidden activations recomputed per tile
        // (cheap: 3-4 FMA each) to keep register pressure low.
#pragma unroll
        for (int tile = 0; tile < 4; tile++) {
            float acc[8];
#pragma unroll
            for (int jj = 0; jj < 8; jj++) acc[jj] = b2[tile * 8 + jj];
#pragma unroll 8
            for (int k = 0; k < 32; k++) {
                float a = xv.x * W1[k] + xv.y * W1[32 + k] + b1[k];
                if (bd) a += yv * W1[64 + k];
                a = fmaxf(a, 0.0f);
                const float* wrow = W2 + k * 32 + tile * 8;
#pragma unroll
                for (int jj = 0; jj < 8; jj++) acc[jj] += a * wrow[jj];
            }
            hp[tile * 2 + 0] = make_float4(fmaxf(acc[0], 0.0f), fmaxf(acc[1], 0.0f),
                                           fmaxf(acc[2], 0.0f), fmaxf(acc[3], 0.0f));
            hp[tile * 2 + 1] = make_float4(fmaxf(acc[4], 0.0f), fmaxf(acc[5], 0.0f),
                                           fmaxf(acc[6], 0.0f), fmaxf(acc[7], 0.0f));
        }
    }
    for (int e = gid; e < EE; e += stride) atomicAdd(&g_deg[__ldg(&dst[e])], 1);
    gsync();

    // ===== Phase B: dinv + tile-local exclusive scans =====
    for (int i = gid; i < NN; i += stride)
        g_dinv[i] = rsqrtf((float)(g_deg[i] + 1));
    for (int tile = blockIdx.x; tile < NTILE; tile += gridDim.x) {
        __syncthreads();
        int base = tile * 1024 + tid * 4;
        int v[4];
#pragma unroll
        for (int r = 0; r < 4; r++) v[r] = (base + r < NN) ? g_deg[base + r] : 0;
        int ts = v[0] + v[1] + v[2] + v[3];
        sInt[tid] = ts;
        __syncthreads();
#pragma unroll
        for (int d = 1; d < 256; d <<= 1) {
            int t2 = (tid >= d) ? sInt[tid - d] : 0;
            __syncthreads();
            sInt[tid] += t2;
            __syncthreads();
        }
        int run = sInt[tid] - ts;   // exclusive prefix of this thread's chunk
#pragma unroll
        for (int r = 0; r < 4; r++) {
            if (base + r < NN) g_rowptr[base + r] = run;
            run += v[r];
        }
        if (tid == 255) g_blocksums[tile] = sInt[255];
    }
    gsync();

    // ===== Phase C: scan of tile sums (block 0 only) =====
    if (blockIdx.x == 0) {
        int v = (tid < NTILE) ? g_blocksums[tid] : 0;
        sInt[tid] = v;
        __syncthreads();
#pragma unroll
        for (int d = 1; d < 256; d <<= 1) {
            int t2 = (tid >= d) ? sInt[tid - d] : 0;
            __syncthreads();
            sInt[tid] += t2;
            __syncthreads();
        }
        if (tid < NTILE) g_blocksums[tid] = sInt[tid] - v;  // exclusive
    }
    gsync();

    // ===== Phase D: finalize rowptr, cursor; reset deg for next call =====
    for (int i = gid; i < NN; i += stride) {
        int r = g_rowptr[i] + g_blocksums[i >> 10];
        g_rowptr[i] = r;
        g_cursor[i] = r;
        g_deg[i] = 0;
    }
    if (gid == 0) g_rowptr[NN] = EE;
    gsync();

    // ===== Phase E: CSR bucket fill =====
    for (int e = gid; e < EE; e += stride) {
        int s = __ldg(&src[e]);
        int d = __ldg(&dst[e]);
        int pos = atomicAdd(&g_cursor[d], 1);
        g_csri[pos] = s;
    }
    gsync();

    // ===== Convs =====
    xform_phase(g_h0, Wc1, smem); gsync();
    gather_phase(g_h1, bc1);      gsync();
    xform_phase(g_h1, Wc2, smem); gsync();
    gather_phase(g_h0, bc2);      gsync();
    xform_phase(g_h0, Wc3, smem); gsync();
    gather_phase(g_h1, bc3);      gsync();

    // ===== Head: out[i] = dot(relu(h1[i]), Wf) + bf =====
    if (tid < 32) smem[tid] = Wf[tid];
    if (tid == 32) smem[32] = bf[0];
    __syncthreads();
    for (int i = gid; i < NN; i += stride) {
        const float4* hp = (const float4*)(g_h1 + i * HH);
        float acc = smem[32];
#pragma unroll
        for (int q = 0; q < 8; q++) {
            float4 v = hp[q];
            acc += fmaxf(v.x, 0.0f) * smem[4 * q + 0];
            acc += fmaxf(v.y, 0.0f) * smem[4 * q + 1];
            acc += fmaxf(v.z, 0.0f) * smem[4 * q + 2];
            acc += fmaxf(v.w, 0.0f) * smem[4 * q + 3];
        }
        out[i] = acc;
    }
}

extern "C" void kernel_launch(void* const* d_in, const int* in_sizes, int n_in,
                              void* d_out, int out_size) {
    const float* x    = (const float*)d_in[0];
    const float* y    = (const float*)d_in[1];
    const int*   ei   = (const int*)d_in[2];
    const int*   bidx = (const int*)d_in[3];
    const int*   iidx = (const int*)d_in[4];
    const float* Wb1 = (const float*)d_in[5];
    const float* bb1 = (const float*)d_in[6];
    const float* Wb2 = (const float*)d_in[7];
    const float* bb2 = (const float*)d_in[8];
    const float* Wi1 = (const float*)d_in[9];
    const float* bi1 = (const float*)d_in[10];
    const float* Wi2 = (const float*)d_in[11];
    const float* bi2 = (const float*)d_in[12];
    const float* Wc1 = (const float*)d_in[13];
    const float* bc1 = (const float*)d_in[14];
    const float* Wc2 = (const float*)d_in[15];
    const float* bc2 = (const float*)d_in[16];
    const float* Wc3 = (const float*)d_in[17];
    const float* bc3 = (const float*)d_in[18];
    const float* Wf  = (const float*)d_in[19];
    const float* bf  = (const float*)d_in[20];

    int NB = in_sizes[3];
    const int* src = ei;        // edge_index[0,:]
    const int* dst = ei + EE;   // edge_index[1,:]

    // Exactly-resident grid for the software grid barrier.
    int dev = 0;
    cudaGetDevice(&dev);
    int sms = 148;
    cudaDeviceGetAttribute(&sms, cudaDevAttrMultiProcessorCount, dev);
    int per = 1;
    cudaOccupancyMaxActiveBlocksPerMultiprocessor(&per, fused_kernel, 256, 0);
    if (per < 1) per = 1;
    int nblk = sms * per;

    fused_kernel<<<nblk, 256>>>(x, y, src, dst, bidx, iidx, NB,
                                Wb1, bb1, Wb2, bb2, Wi1, bi1, Wi2, bi2,
                                Wc1, bc1, Wc2, bc2, Wc3, bc3, Wf, bf,
                                (float*)d_out);
}

// round 7
// speedup vs baseline: 3.7213x; 3.4299x over previous
#include <cuda_runtime.h>
#include <cuda_bf16.h>
#include <cuda_fp16.h>

// Problem constants (fixed by the dataset)
#define NN 100000
#define EE 1600000
#define HH 32
#define NTILE 98                       // ceil(NN / 1024)

#define CDIV(a, b) (((a) + (b) - 1) / (b))

// Scratch (static device globals; no allocation allowed)
__device__ int    g_deg[NN];           // zero at entry (static init / reset by scan3)
__device__ int    g_rowptr[NN + 1];
__device__ int    g_cursor[NN];
__device__ int    g_blocksums[NTILE];
__device__ float  g_dinv[NN];
__device__ int    g_csri[EE];          // src indices, bucketed by dst
__device__ float  g_h0[NN * HH];       // ping
__device__ float  g_h1[NN * HH];       // pong
__device__ __half g_t[NN * HH];        // t'[i] = (relu(h[i]) @ W) * dinv[i], fp16

__device__ __forceinline__ float* hbuf(int s) { return s ? g_h1 : g_h0; }

// ---------------------------------------------------------------------------
// 1) Degree count per dst (int atomics). g_deg is zero at entry.
// ---------------------------------------------------------------------------
__global__ void deg_kernel(const int* __restrict__ dst) {
    int e = blockIdx.x * blockDim.x + threadIdx.x;
    if (e < EE) atomicAdd(&g_deg[dst[e]], 1);
}

// ---------------------------------------------------------------------------
// 2) dinv + tile-local exclusive scan (one block per 1024-node tile).
// ---------------------------------------------------------------------------
__global__ void scan1_kernel() {
    __shared__ int sInt[256];
    int tid = threadIdx.x;
    int base = blockIdx.x * 1024 + tid * 4;
    int v[4];
#pragma unroll
    for (int r = 0; r < 4; r++) {
        int i = base + r;
        v[r] = (i < NN) ? g_deg[i] : 0;
        if (i < NN) g_dinv[i] = rsqrtf((float)(v[r] + 1));
    }
    int ts = v[0] + v[1] + v[2] + v[3];
    sInt[tid] = ts;
    __syncthreads();
#pragma unroll
    for (int d = 1; d < 256; d <<= 1) {
        int t2 = (tid >= d) ? sInt[tid - d] : 0;
        __syncthreads();
        sInt[tid] += t2;
        __syncthreads();
    }
    int run = sInt[tid] - ts;  // exclusive prefix of this thread's chunk in tile
#pragma unroll
    for (int r = 0; r < 4; r++) {
        if (base + r < NN) g_rowptr[base + r] = run;
        run += v[r];
    }
    if (tid == 255) g_blocksums[blockIdx.x] = sInt[255];
}

// ---------------------------------------------------------------------------
// 3) Finalize rowptr: every block redundantly scans the 98 tile sums in smem
//    (cheap), then adds the tile offset. Also init cursor + reset deg.
// ---------------------------------------------------------------------------
__global__ void scan3_kernel() {
    __shared__ int s[128];
    int tid = threadIdx.x;
    if (tid < 128) s[tid] = (tid < NTILE) ? g_blocksums[tid] : 0;
    __syncthreads();
    // Hillis-Steele inclusive scan over 128 entries (first 128 threads)
#pragma unroll
    for (int d = 1; d < 128; d <<= 1) {
        int t2 = (tid < 128 && tid >= d) ? s[tid - d] : 0;
        __syncthreads();
        if (tid < 128) s[tid] += t2;
        __syncthreads();
    }
    int i = blockIdx.x * blockDim.x + tid;
    if (i < NN) {
        int tile = i >> 10;
        int off = (tile == 0) ? 0 : s[tile - 1];   // exclusive
        int r = g_rowptr[i] + off;
        g_rowptr[i] = r;
        g_cursor[i] = r;
        g_deg[i] = 0;                               // ready for next call
    }
    if (i == 0) g_rowptr[NN] = EE;
}

// ---------------------------------------------------------------------------
// 4) Bucket-fill CSR (src index only; norm folded into t' and dinv[dst]).
// ---------------------------------------------------------------------------
__global__ void fill_kernel(const int* __restrict__ src, const int* __restrict__ dst) {
    int e = blockIdx.x * blockDim.x + threadIdx.x;
    if (e >= EE) return;
    int s = __ldg(&src[e]);
    int d = __ldg(&dst[e]);
    int pos = atomicAdd(&g_cursor[d], 1);
    g_csri[pos] = s;
}

// ---------------------------------------------------------------------------
// 5) Encoders (both) in one kernel: j < NB -> boundary MLP, else interior.
//    Output tiled in chunks of 8 columns to keep registers modest.
// ---------------------------------------------------------------------------
__global__ void enc_kernel(const float* __restrict__ x, const float* __restrict__ y,
                           const int* __restrict__ bidx, const int* __restrict__ iidx,
                           int NB,
                           const float* __restrict__ Wb1, const float* __restrict__ bb1,
                           const float* __restrict__ Wb2, const float* __restrict__ bb2,
                           const float* __restrict__ Wi1, const float* __restrict__ bi1,
                           const float* __restrict__ Wi2, const float* __restrict__ bi2) {
    __shared__ float smem[2336];
    int tid = threadIdx.x;
    for (int i = tid; i < 96; i += blockDim.x) smem[i] = Wb1[i];
    for (int i = tid; i < 64; i += blockDim.x) smem[1184 + i] = Wi1[i];
    for (int i = tid; i < 32; i += blockDim.x) {
        smem[96 + i] = bb1[i];   smem[1152 + i] = bb2[i];
        smem[1248 + i] = bi1[i]; smem[2304 + i] = bi2[i];
    }
    for (int i = tid; i < 1024; i += blockDim.x) {
        smem[128 + i] = Wb2[i];
        smem[1280 + i] = Wi2[i];
    }
    __syncthreads();

    int j = blockIdx.x * blockDim.x + tid;
    if (j >= NN) return;
    bool bd = j < NB;
    int node = bd ? __ldg(&bidx[j]) : __ldg(&iidx[j - NB]);
    const float* W1 = bd ? smem : smem + 1184;
    const float* b1 = bd ? smem + 96 : smem + 1248;
    const float* W2 = bd ? smem + 128 : smem + 1280;
    const float* b2 = bd ? smem + 1152 : smem + 2304;
    float2 xv = __ldg((const float2*)x + node);
    float yv = bd ? __ldg(&y[node]) : 0.0f;

    float4* hp = (float4*)&g_h0[node * HH];
#pragma unroll
    for (int tile = 0; tile < 4; tile++) {
        float acc[8];
#pragma unroll
        for (int jj = 0; jj < 8; jj++) acc[jj] = b2[tile * 8 + jj];
#pragma unroll 8
        for (int k = 0; k < 32; k++) {
            float a = xv.x * W1[k] + xv.y * W1[32 + k] + b1[k];
            if (bd) a += yv * W1[64 + k];
            a = fmaxf(a, 0.0f);
            const float* wrow = W2 + k * 32 + tile * 8;
#pragma unroll
            for (int jj = 0; jj < 8; jj++) acc[jj] += a * wrow[jj];
        }
        hp[tile * 2 + 0] = make_float4(fmaxf(acc[0], 0.0f), fmaxf(acc[1], 0.0f),
                                       fmaxf(acc[2], 0.0f), fmaxf(acc[3], 0.0f));
        hp[tile * 2 + 1] = make_float4(fmaxf(acc[4], 0.0f), fmaxf(acc[5], 0.0f),
                                       fmaxf(acc[6], 0.0f), fmaxf(acc[7], 0.0f));
    }
}

// ---------------------------------------------------------------------------
// Dense transform: t'[i] = (relu(hin[i]) @ W) * dinv[i], stored fp16.
// ---------------------------------------------------------------------------
__global__ void xform_kernel(int in_sel, const float* __restrict__ W) {
    __shared__ float sW[1024];
    int t = threadIdx.x;
    for (int i = t; i < 1024; i += blockDim.x) sW[i] = W[i];
    __syncthreads();

    int i = blockIdx.x * blockDim.x + t;
    if (i >= NN) return;
    const float* hin = hbuf(in_sel);

    float acc[32];
#pragma unroll
    for (int jj = 0; jj < 32; jj++) acc[jj] = 0.0f;

    const float4* hp = (const float4*)(hin + i * HH);
#pragma unroll
    for (int q = 0; q < 8; q++) {
        float4 v4 = hp[q];
        float vv[4] = {fmaxf(v4.x, 0.0f), fmaxf(v4.y, 0.0f), fmaxf(v4.z, 0.0f), fmaxf(v4.w, 0.0f)};
#pragma unroll
        for (int r = 0; r < 4; r++) {
            float v = vv[r];
            int k = 4 * q + r;
#pragma unroll
            for (int jj = 0; jj < 32; jj++) acc[jj] += v * sW[k * 32 + jj];
        }
    }
    float di = g_dinv[i];
    __half2* tp = (__half2*)&g_t[i * HH];
#pragma unroll
    for (int q = 0; q < 16; q++)
        tp[q] = __float22half2_rn(make_float2(acc[2 * q] * di, acc[2 * q + 1] * di));
}

// ---------------------------------------------------------------------------
// 16-lane-per-node gather (no atomics), edge loop unrolled x4 for MLP:
//   hout[i] = b + dinv[i] * ( t'[i] + sum_{e in in(i)} t'[src(e)] )
// Each lane owns 2 columns (one half2 = 4B load). Per edge: 4B bcast + 64B row.
// ---------------------------------------------------------------------------
__global__ void gather_kernel(int out_sel, const float* __restrict__ b) {
    int gid = blockIdx.x * blockDim.x + threadIdx.x;
    int node = gid >> 4, sub = gid & 15;
    if (node >= NN) return;

    const __half2* tp = (const __half2*)g_t;
    float2 a0 = __half22float2(__ldg(tp + node * 16 + sub));   // self term
    float2 a1 = make_float2(0.0f, 0.0f);
    float2 a2 = make_float2(0.0f, 0.0f);
    float2 a3 = make_float2(0.0f, 0.0f);

    int e = __ldg(&g_rowptr[node]);
    int e1 = __ldg(&g_rowptr[node + 1]);
    for (; e + 3 < e1; e += 4) {
        int s0 = __ldg(&g_csri[e]);
        int s1 = __ldg(&g_csri[e + 1]);
        int s2 = __ldg(&g_csri[e + 2]);
        int s3 = __ldg(&g_csri[e + 3]);
        float2 v0 = __half22float2(__ldg(tp + s0 * 16 + sub));
        float2 v1 = __half22float2(__ldg(tp + s1 * 16 + sub));
        float2 v2 = __half22float2(__ldg(tp + s2 * 16 + sub));
        float2 v3 = __half22float2(__ldg(tp + s3 * 16 + sub));
        a0.x += v0.x; a0.y += v0.y;
        a1.x += v1.x; a1.y += v1.y;
        a2.x += v2.x; a2.y += v2.y;
        a3.x += v3.x; a3.y += v3.y;
    }
    for (; e < e1; e++) {
        int s0 = __ldg(&g_csri[e]);
        float2 v0 = __half22float2(__ldg(tp + s0 * 16 + sub));
        a0.x += v0.x; a0.y += v0.y;
    }
    float di = g_dinv[node];
    float2 bb = __ldg((const float2*)b + sub);
    float sx = a0.x + a1.x + a2.x + a3.x;
    float sy = a0.y + a1.y + a2.y + a3.y;
    ((float2*)hbuf(out_sel))[node * 16 + sub] = make_float2(bb.x + di * sx, bb.y + di * sy);
}

// Head: out[i] = dot(relu(h[i]), Wf) + bf
__global__ void final_kernel(int in_sel, const float* __restrict__ Wf,
                             const float* __restrict__ bf, float* __restrict__ out) {
    __shared__ float sw[32];
    __shared__ float sbf;
    int t = threadIdx.x;
    if (t < 32) sw[t] = Wf[t];
    if (t == 0) sbf = bf[0];
    __syncthreads();

    int i = blockIdx.x * blockDim.x + t;
    if (i >= NN) return;
    const float4* hp = (const float4*)(hbuf(in_sel) + i * HH);
    float acc = sbf;
#pragma unroll
    for (int q = 0; q < 8; q++) {
        float4 v = hp[q];
        acc += fmaxf(v.x, 0.0f) * sw[4 * q + 0];
        acc += fmaxf(v.y, 0.0f) * sw[4 * q + 1];
        acc += fmaxf(v.z, 0.0f) * sw[4 * q + 2];
        acc += fmaxf(v.w, 0.0f) * sw[4 * q + 3];
    }
    out[i] = acc;
}

extern "C" void kernel_launch(void* const* d_in, const int* in_sizes, int n_in,
                              void* d_out, int out_size) {
    const float* x    = (const float*)d_in[0];
    const float* y    = (const float*)d_in[1];
    const int*   ei   = (const int*)d_in[2];
    const int*   bidx = (const int*)d_in[3];
    const int*   iidx = (const int*)d_in[4];
    const float* Wb1 = (const float*)d_in[5];
    const float* bb1 = (const float*)d_in[6];
    const float* Wb2 = (const float*)d_in[7];
    const float* bb2 = (const float*)d_in[8];
    const float* Wi1 = (const float*)d_in[9];
    const float* bi1 = (const float*)d_in[10];
    const float* Wi2 = (const float*)d_in[11];
    const float* bi2 = (const float*)d_in[12];
    const float* Wc1 = (const float*)d_in[13];
    const float* bc1 = (const float*)d_in[14];
    const float* Wc2 = (const float*)d_in[15];
    const float* bc2 = (const float*)d_in[16];
    const float* Wc3 = (const float*)d_in[17];
    const float* bc3 = (const float*)d_in[18];
    const float* Wf  = (const float*)d_in[19];
    const float* bf  = (const float*)d_in[20];

    int NB = in_sizes[3];
    const int* src = ei;        // edge_index[0,:]
    const int* dst = ei + EE;   // edge_index[1,:]

    // CSR pipeline first (independent of encoders)
    deg_kernel<<<CDIV(EE, 256), 256>>>(dst);                 // 1
    scan1_kernel<<<NTILE, 256>>>();                          // 2 (dinv + tile scan)
    scan3_kernel<<<CDIV(NN, 256), 256>>>();                  // 3
    fill_kernel<<<CDIV(EE, 256), 256>>>(src, dst);           // 4  <- profiled slot

    // Encoders (both in one kernel)
    enc_kernel<<<CDIV(NN, 128), 128>>>(x, y, bidx, iidx, NB,
                                       Wb1, bb1, Wb2, bb2, Wi1, bi1, Wi2, bi2);  // 5

    // Conv 1: h0 -> h1
    xform_kernel<<<CDIV(NN, 128), 128>>>(0, Wc1);            // 6
    gather_kernel<<<CDIV(NN * 16, 256), 256>>>(1, bc1);      // 7
    // Conv 2: h1 -> h0
    xform_kernel<<<CDIV(NN, 128), 128>>>(1, Wc2);            // 8
    gather_kernel<<<CDIV(NN * 16, 256), 256>>>(0, bc2);      // 9
    // Conv 3: h0 -> h1
    xform_kernel<<<CDIV(NN, 128), 128>>>(0, Wc3);            // 10
    gather_kernel<<<CDIV(NN * 16, 256), 256>>>(1, bc3);      // 11

    // Head
    final_kernel<<<CDIV(NN, 256), 256>>>(1, Wf, bf, (float*)d_out);  // 12
}

// round 9
// speedup vs baseline: 4.3167x; 1.1600x over previous
#include <cuda_runtime.h>
#include <cuda_bf16.h>
#include <cuda_fp16.h>

// Problem constants (fixed by the dataset)
#define NN 100000
#define EE 1600000
#define HH 32
#define NTILE 98                       // ceil(NN / 1024)

#define CDIV(a, b) (((a) + (b) - 1) / (b))

// Scratch (static device globals; no allocation allowed)
__device__ int    g_deg[NN];           // zero at entry (static init / reset by scan3)
__device__ int    g_rowptr[NN + 1];
__device__ int    g_cursor[NN];
__device__ int    g_blocksums[NTILE];
__device__ float  g_dinv[NN];
__device__ int    g_csri[EE];          // src indices, bucketed by dst
__device__ float  g_h0[NN * HH];       // ping
__device__ float  g_h1[NN * HH];       // pong
__device__ __half g_t[NN * HH];        // t'[i] = (relu(h[i]) @ W) * dinv[i], fp16

__device__ __forceinline__ float* hbuf(int s) { return s ? g_h1 : g_h0; }

// ---------------------------------------------------------------------------
// 1) Degree count per dst (int atomics). g_deg is zero at entry.
// ---------------------------------------------------------------------------
__global__ void deg_kernel(const int* __restrict__ dst) {
    int e = blockIdx.x * blockDim.x + threadIdx.x;
    if (e < EE) atomicAdd(&g_deg[dst[e]], 1);
}

// ---------------------------------------------------------------------------
// 2) dinv + tile-local exclusive scan (one block per 1024-node tile).
// ---------------------------------------------------------------------------
__global__ void scan1_kernel() {
    __shared__ int sInt[256];
    int tid = threadIdx.x;
    int base = blockIdx.x * 1024 + tid * 4;
    int v[4];
#pragma unroll
    for (int r = 0; r < 4; r++) {
        int i = base + r;
        v[r] = (i < NN) ? g_deg[i] : 0;
        if (i < NN) g_dinv[i] = rsqrtf((float)(v[r] + 1));
    }
    int ts = v[0] + v[1] + v[2] + v[3];
    sInt[tid] = ts;
    __syncthreads();
#pragma unroll
    for (int d = 1; d < 256; d <<= 1) {
        int t2 = (tid >= d) ? sInt[tid - d] : 0;
        __syncthreads();
        sInt[tid] += t2;
        __syncthreads();
    }
    int run = sInt[tid] - ts;  // exclusive prefix of this thread's chunk in tile
#pragma unroll
    for (int r = 0; r < 4; r++) {
        if (base + r < NN) g_rowptr[base + r] = run;
        run += v[r];
    }
    if (tid == 255) g_blocksums[blockIdx.x] = sInt[255];
}

// ---------------------------------------------------------------------------
// 3) Finalize rowptr: every block redundantly scans the 98 tile sums in smem
//    (cheap), then adds the tile offset. Also init cursor + reset deg.
// ---------------------------------------------------------------------------
__global__ void scan3_kernel() {
    __shared__ int s[128];
    int tid = threadIdx.x;
    if (tid < 128) s[tid] = (tid < NTILE) ? g_blocksums[tid] : 0;
    __syncthreads();
#pragma unroll
    for (int d = 1; d < 128; d <<= 1) {
        int t2 = (tid < 128 && tid >= d) ? s[tid - d] : 0;
        __syncthreads();
        if (tid < 128) s[tid] += t2;
        __syncthreads();
    }
    int i = blockIdx.x * blockDim.x + tid;
    if (i < NN) {
        int tile = i >> 10;
        int off = (tile == 0) ? 0 : s[tile - 1];   // exclusive
        int r = g_rowptr[i] + off;
        g_rowptr[i] = r;
        g_cursor[i] = r;
        g_deg[i] = 0;                               // ready for next call
    }
    if (i == 0) g_rowptr[NN] = EE;
}

// ---------------------------------------------------------------------------
// 4) Bucket-fill CSR (src index only; norm folded into t' and dinv[dst]).
// ---------------------------------------------------------------------------
__global__ void fill_kernel(const int* __restrict__ src, const int* __restrict__ dst) {
    int e = blockIdx.x * blockDim.x + threadIdx.x;
    if (e >= EE) return;
    int s = __ldg(&src[e]);
    int d = __ldg(&dst[e]);
    int pos = atomicAdd(&g_cursor[d], 1);
    g_csri[pos] = s;
}

// ---------------------------------------------------------------------------
// 5) Encoders (both) in one kernel: j < NB -> boundary MLP, else interior.
// ---------------------------------------------------------------------------
__global__ void enc_kernel(const float* __restrict__ x, const float* __restrict__ y,
                           const int* __restrict__ bidx, const int* __restrict__ iidx,
                           int NB,
                           const float* __restrict__ Wb1, const float* __restrict__ bb1,
                           const float* __restrict__ Wb2, const float* __restrict__ bb2,
                           const float* __restrict__ Wi1, const float* __restrict__ bi1,
                           const float* __restrict__ Wi2, const float* __restrict__ bi2) {
    __shared__ float smem[2336];
    int tid = threadIdx.x;
    for (int i = tid; i < 96; i += blockDim.x) smem[i] = Wb1[i];
    for (int i = tid; i < 64; i += blockDim.x) smem[1184 + i] = Wi1[i];
    for (int i = tid; i < 32; i += blockDim.x) {
        smem[96 + i] = bb1[i];   smem[1152 + i] = bb2[i];
        smem[1248 + i] = bi1[i]; smem[2304 + i] = bi2[i];
    }
    for (int i = tid; i < 1024; i += blockDim.x) {
        smem[128 + i] = Wb2[i];
        smem[1280 + i] = Wi2[i];
    }
    __syncthreads();

    int j = blockIdx.x * blockDim.x + tid;
    if (j >= NN) return;
    bool bd = j < NB;
    int node = bd ? __ldg(&bidx[j]) : __ldg(&iidx[j - NB]);
    const float* W1 = bd ? smem : smem + 1184;
    const float* b1 = bd ? smem + 96 : smem + 1248;
    const float* W2 = bd ? smem + 128 : smem + 1280;
    const float* b2 = bd ? smem + 1152 : smem + 2304;
    float2 xv = __ldg((const float2*)x + node);
    float yv = bd ? __ldg(&y[node]) : 0.0f;

    float4* hp = (float4*)&g_h0[node * HH];
#pragma unroll
    for (int tile = 0; tile < 4; tile++) {
        float acc[8];
#pragma unroll
        for (int jj = 0; jj < 8; jj++) acc[jj] = b2[tile * 8 + jj];
#pragma unroll 8
        for (int k = 0; k < 32; k++) {
            float a = xv.x * W1[k] + xv.y * W1[32 + k] + b1[k];
            if (bd) a += yv * W1[64 + k];
            a = fmaxf(a, 0.0f);
            const float* wrow = W2 + k * 32 + tile * 8;
#pragma unroll
            for (int jj = 0; jj < 8; jj++) acc[jj] += a * wrow[jj];
        }
        hp[tile * 2 + 0] = make_float4(fmaxf(acc[0], 0.0f), fmaxf(acc[1], 0.0f),
                                       fmaxf(acc[2], 0.0f), fmaxf(acc[3], 0.0f));
        hp[tile * 2 + 1] = make_float4(fmaxf(acc[4], 0.0f), fmaxf(acc[5], 0.0f),
                                       fmaxf(acc[6], 0.0f), fmaxf(acc[7], 0.0f));
    }
}

// ---------------------------------------------------------------------------
// Dense transform: t'[i] = (relu(hin[i]) @ W) * dinv[i], stored fp16.
// ---------------------------------------------------------------------------
__global__ void xform_kernel(int in_sel, const float* __restrict__ W) {
    __shared__ float sW[1024];
    int t = threadIdx.x;
    for (int i = t; i < 1024; i += blockDim.x) sW[i] = W[i];
    __syncthreads();

    int i = blockIdx.x * blockDim.x + t;
    if (i >= NN) return;
    const float* hin = hbuf(in_sel);

    float acc[32];
#pragma unroll
    for (int jj = 0; jj < 32; jj++) acc[jj] = 0.0f;

    const float4* hp = (const float4*)(hin + i * HH);
#pragma unroll
    for (int q = 0; q < 8; q++) {
        float4 v4 = hp[q];
        float vv[4] = {fmaxf(v4.x, 0.0f), fmaxf(v4.y, 0.0f), fmaxf(v4.z, 0.0f), fmaxf(v4.w, 0.0f)};
#pragma unroll
        for (int r = 0; r < 4; r++) {
            float v = vv[r];
            int k = 4 * q + r;
#pragma unroll
            for (int jj = 0; jj < 32; jj++) acc[jj] += v * sW[k * 32 + jj];
        }
    }
    float di = g_dinv[i];
    __half2* tp = (__half2*)&g_t[i * HH];
#pragma unroll
    for (int q = 0; q < 16; q++)
        tp[q] = __float22half2_rn(make_float2(acc[2 * q] * di, acc[2 * q + 1] * di));
}

// ---------------------------------------------------------------------------
// 4-lane-per-node gather (no atomics). Lane sub owns 8 columns (one uint4 =
// 16B = 8 halves per row load). Per warp iteration: 8 LDG instructions cover
// 32 edges (8 nodes x 4 edges) -> ~0.25 LDG/edge vs ~1 for the 16-lane form.
//   hout[i] = b + dinv[i] * ( t'[i] + sum_{e in in(i)} t'[src(e)] )
// ---------------------------------------------------------------------------
__device__ __forceinline__ void addu4(float4& a, float4& b, uint4 u) {
    const __half2* h = (const __half2*)&u;
    float2 f0 = __half22float2(h[0]);
    float2 f1 = __half22float2(h[1]);
    float2 f2 = __half22float2(h[2]);
    float2 f3 = __half22float2(h[3]);
    a.x += f0.x; a.y += f0.y; a.z += f1.x; a.w += f1.y;
    b.x += f2.x; b.y += f2.y; b.z += f3.x; b.w += f3.y;
}

__global__ void gather_kernel(int out_sel, const float* __restrict__ b) {
    int gid = blockIdx.x * blockDim.x + threadIdx.x;
    int node = gid >> 2, sub = gid & 3;
    if (node >= NN) return;

    const uint4* tp = (const uint4*)g_t;   // one row = 4 uint4
    float4 aA0 = make_float4(0.f, 0.f, 0.f, 0.f), aA1 = aA0;  // accumulator set A
    float4 aB0 = aA0, aB1 = aA0;                               // accumulator set B

    addu4(aA0, aA1, __ldg(tp + node * 4 + sub));               // self term

    int e = __ldg(&g_rowptr[node]);
    int e1 = __ldg(&g_rowptr[node + 1]);
    for (; e + 3 < e1; e += 4) {
        int s0 = __ldg(&g_csri[e + 0]);
        int s1 = __ldg(&g_csri[e + 1]);
        int s2 = __ldg(&g_csri[e + 2]);
        int s3 = __ldg(&g_csri[e + 3]);
        uint4 u0 = __ldg(tp + s0 * 4 + sub);
        uint4 u1 = __ldg(tp + s1 * 4 + sub);
        uint4 u2 = __ldg(tp + s2 * 4 + sub);
        uint4 u3 = __ldg(tp + s3 * 4 + sub);
        addu4(aA0, aA1, u0);
        addu4(aB0, aB1, u1);
        addu4(aA0, aA1, u2);
        addu4(aB0, aB1, u3);
    }
    for (; e < e1; e++) {
        addu4(aA0, aA1, __ldg(tp + __ldg(&g_csri[e]) * 4 + sub));
    }
    float di = g_dinv[node];
    const float4* bp = (const float4*)b;   // bias chunk for lane: [sub*8, sub*8+8)
    float4 b0 = __ldg(bp + sub * 2 + 0);
    float4 b1 = __ldg(bp + sub * 2 + 1);
    float4 o0 = make_float4(b0.x + di * (aA0.x + aB0.x), b0.y + di * (aA0.y + aB0.y),
                            b0.z + di * (aA0.z + aB0.z), b0.w + di * (aA0.w + aB0.w));
    float4 o1 = make_float4(b1.x + di * (aA1.x + aB1.x), b1.y + di * (aA1.y + aB1.y),
                            b1.z + di * (aA1.z + aB1.z), b1.w + di * (aA1.w + aB1.w));
    float4* op = (float4*)hbuf(out_sel);
    op[node * 8 + sub * 2 + 0] = o0;
    op[node * 8 + sub * 2 + 1] = o1;
}

// Head: out[i] = dot(relu(h[i]), Wf) + bf
__global__ void final_kernel(int in_sel, const float* __restrict__ Wf,
                             const float* __restrict__ bf, float* __restrict__ out) {
    __shared__ float sw[32];
    __shared__ float sbf;
    int t = threadIdx.x;
    if (t < 32) sw[t] = Wf[t];
    if (t == 0) sbf = bf[0];
    __syncthreads();

    int i = blockIdx.x * blockDim.x + t;
    if (i >= NN) return;
    const float4* hp = (const float4*)(hbuf(in_sel) + i * HH);
    float acc = sbf;
#pragma unroll
    for (int q = 0; q < 8; q++) {
        float4 v = hp[q];
        acc += fmaxf(v.x, 0.0f) * sw[4 * q + 0];
        acc += fmaxf(v.y, 0.0f) * sw[4 * q + 1];
        acc += fmaxf(v.z, 0.0f) * sw[4 * q + 2];
        acc += fmaxf(v.w, 0.0f) * sw[4 * q + 3];
    }
    out[i] = acc;
}

extern "C" void kernel_launch(void* const* d_in, const int* in_sizes, int n_in,
                              void* d_out, int out_size) {
    const float* x    = (const float*)d_in[0];
    const float* y    = (const float*)d_in[1];
    const int*   ei   = (const int*)d_in[2];
    const int*   bidx = (const int*)d_in[3];
    const int*   iidx = (const int*)d_in[4];
    const float* Wb1 = (const float*)d_in[5];
    const float* bb1 = (const float*)d_in[6];
    const float* Wb2 = (const float*)d_in[7];
    const float* bb2 = (const float*)d_in[8];
    const float* Wi1 = (const float*)d_in[9];
    const float* bi1 = (const float*)d_in[10];
    const float* Wi2 = (const float*)d_in[11];
    const float* bi2 = (const float*)d_in[12];
    const float* Wc1 = (const float*)d_in[13];
    const float* bc1 = (const float*)d_in[14];
    const float* Wc2 = (const float*)d_in[15];
    const float* bc2 = (const float*)d_in[16];
    const float* Wc3 = (const float*)d_in[17];
    const float* bc3 = (const float*)d_in[18];
    const float* Wf  = (const float*)d_in[19];
    const float* bf  = (const float*)d_in[20];

    int NB = in_sizes[3];
    const int* src = ei;        // edge_index[0,:]
    const int* dst = ei + EE;   // edge_index[1,:]

    // CSR pipeline first (independent of encoders)
    deg_kernel<<<CDIV(EE, 256), 256>>>(dst);                 // 1
    scan1_kernel<<<NTILE, 256>>>();                          // 2 (dinv + tile scan)
    scan3_kernel<<<CDIV(NN, 256), 256>>>();                  // 3
    fill_kernel<<<CDIV(EE, 256), 256>>>(src, dst);           // 4  <- profiled slot

    // Encoders (both in one kernel)
    enc_kernel<<<CDIV(NN, 128), 128>>>(x, y, bidx, iidx, NB,
                                       Wb1, bb1, Wb2, bb2, Wi1, bi1, Wi2, bi2);  // 5

    // Conv 1: h0 -> h1
    xform_kernel<<<CDIV(NN, 128), 128>>>(0, Wc1);            // 6
    gather_kernel<<<CDIV(NN * 4, 256), 256>>>(1, bc1);       // 7
    // Conv 2: h1 -> h0
    xform_kernel<<<CDIV(NN, 128), 128>>>(1, Wc2);            // 8
    gather_kernel<<<CDIV(NN * 4, 256), 256>>>(0, bc2);       // 9
    // Conv 3: h0 -> h1
    xform_kernel<<<CDIV(NN, 128), 128>>>(0, Wc3);            // 10
    gather_kernel<<<CDIV(NN * 4, 256), 256>>>(1, bc3);       // 11

    // Head
    final_kernel<<<CDIV(NN, 256), 256>>>(1, Wf, bf, (float*)d_out);  // 12
}

// round 12
// speedup vs baseline: 5.0156x; 1.1619x over previous
#include <cuda_runtime.h>
#include <cuda_bf16.h>
#include <cuda_fp16.h>

// Problem constants (fixed by the dataset)
#define NN 100000
#define EE 1600000
#define HH 32
#define NTILE 98                       // ceil(NN / 1024)

#define CDIV(a, b) (((a) + (b) - 1) / (b))

// Scratch (static device globals; no allocation allowed)
__device__ int    g_deg[NN];           // zero at entry (static init / reset by scan3)
__device__ int    g_rowptr[NN + 1];
__device__ int    g_cursor[NN];
__device__ int    g_blocksums[NTILE];
__device__ float  g_dinv[NN];
__device__ int    g_csri[EE];          // src indices, bucketed by dst
__device__ __half g_t0[NN * HH];       // t ping (fp16, pre-scaled by dinv[src])
__device__ __half g_t1[NN * HH];       // t pong

// Device-side buffer selection (NEVER pass __device__ globals from host!)
__device__ __forceinline__ __half* tbuf(int s) { return s ? g_t1 : g_t0; }

// ---------------------------------------------------------------------------
// 1) Degree count per dst. 4 edges/thread (int4 load, 4 independent atomics).
// ---------------------------------------------------------------------------
__global__ void deg_kernel(const int* __restrict__ dst) {
    int e4 = (blockIdx.x * blockDim.x + threadIdx.x) * 4;
    if (e4 >= EE) return;
    int4 d = *(const int4*)(dst + e4);
    atomicAdd(&g_deg[d.x], 1);
    atomicAdd(&g_deg[d.y], 1);
    atomicAdd(&g_deg[d.z], 1);
    atomicAdd(&g_deg[d.w], 1);
}

// ---------------------------------------------------------------------------
// 2) dinv + tile-local exclusive scan (one block per 1024-node tile).
// ---------------------------------------------------------------------------
__global__ void scan1_kernel() {
    __shared__ int sInt[256];
    int tid = threadIdx.x;
    int base = blockIdx.x * 1024 + tid * 4;
    int v[4];
#pragma unroll
    for (int r = 0; r < 4; r++) {
        int i = base + r;
        v[r] = (i < NN) ? g_deg[i] : 0;
        if (i < NN) g_dinv[i] = rsqrtf((float)(v[r] + 1));
    }
    int ts = v[0] + v[1] + v[2] + v[3];
    sInt[tid] = ts;
    __syncthreads();
#pragma unroll
    for (int d = 1; d < 256; d <<= 1) {
        int t2 = (tid >= d) ? sInt[tid - d] : 0;
        __syncthreads();
        sInt[tid] += t2;
        __syncthreads();
    }
    int run = sInt[tid] - ts;
#pragma unroll
    for (int r = 0; r < 4; r++) {
        if (base + r < NN) g_rowptr[base + r] = run;
        run += v[r];
    }
    if (tid == 255) g_blocksums[blockIdx.x] = sInt[255];
}

// ---------------------------------------------------------------------------
// 3) Finalize rowptr (every block rescans the 98 tile sums); init cursor,
//    reset deg for the next call.
// ---------------------------------------------------------------------------
__global__ void scan3_kernel() {
    __shared__ int s[128];
    int tid = threadIdx.x;
    if (tid < 128) s[tid] = (tid < NTILE) ? g_blocksums[tid] : 0;
    __syncthreads();
#pragma unroll
    for (int d = 1; d < 128; d <<= 1) {
        int t2 = (tid < 128 && tid >= d) ? s[tid - d] : 0;
        __syncthreads();
        if (tid < 128) s[tid] += t2;
        __syncthreads();
    }
    int i = blockIdx.x * blockDim.x + tid;
    if (i < NN) {
        int tile = i >> 10;
        int off = (tile == 0) ? 0 : s[tile - 1];
        int r = g_rowptr[i] + off;
        g_rowptr[i] = r;
        g_cursor[i] = r;
        g_deg[i] = 0;
    }
    if (i == 0) g_rowptr[NN] = EE;
}

// ---------------------------------------------------------------------------
// 4) Bucket-fill CSR, 4 edges/thread.
// ---------------------------------------------------------------------------
__global__ void fill_kernel(const int* __restrict__ src, const int* __restrict__ dst) {
    int e4 = (blockIdx.x * blockDim.x + threadIdx.x) * 4;
    if (e4 >= EE) return;
    int4 s = *(const int4*)(src + e4);
    int4 d = *(const int4*)(dst + e4);
    int p0 = atomicAdd(&g_cursor[d.x], 1);
    int p1 = atomicAdd(&g_cursor[d.y], 1);
    int p2 = atomicAdd(&g_cursor[d.z], 1);
    int p3 = atomicAdd(&g_cursor[d.w], 1);
    g_csri[p0] = s.x;
    g_csri[p1] = s.y;
    g_csri[p2] = s.z;
    g_csri[p3] = s.w;
}

// Pack two floats into one fp16x2 word (scalar reinterpret; stays in regs).
__device__ __forceinline__ unsigned pk(float x, float y) {
    __half2 h = __float22half2_rn(make_float2(x, y));
    return *reinterpret_cast<unsigned*>(&h);
}

// ---------------------------------------------------------------------------
// 5) Encoder + xform1 fused: h = MLP(node feats) (relu'd), then
//    t0 = (h @ Wc1) * dinv, written fp16. h never touches memory.
// ---------------------------------------------------------------------------
__global__ void enc_x1_kernel(const float* __restrict__ x, const float* __restrict__ y,
                              const int* __restrict__ bidx, const int* __restrict__ iidx,
                              int NB,
                              const float* __restrict__ Wb1, const float* __restrict__ bb1,
                              const float* __restrict__ Wb2, const float* __restrict__ bb2,
                              const float* __restrict__ Wi1, const float* __restrict__ bi1,
                              const float* __restrict__ Wi2, const float* __restrict__ bi2,
                              const float* __restrict__ Wc1) {
    __shared__ float smem[3360];   // [0:2336) encoder weights, [2336:3360) Wc1
    int tid = threadIdx.x;
    for (int i = tid; i < 96; i += blockDim.x) smem[i] = Wb1[i];
    for (int i = tid; i < 64; i += blockDim.x) smem[1184 + i] = Wi1[i];
    for (int i = tid; i < 32; i += blockDim.x) {
        smem[96 + i] = bb1[i];   smem[1152 + i] = bb2[i];
        smem[1248 + i] = bi1[i]; smem[2304 + i] = bi2[i];
    }
    for (int i = tid; i < 1024; i += blockDim.x) {
        smem[128 + i] = Wb2[i];
        smem[1280 + i] = Wi2[i];
        smem[2336 + i] = Wc1[i];
    }
    __syncthreads();

    int j = blockIdx.x * blockDim.x + tid;
    if (j >= NN) return;
    bool bd = j < NB;
    int node = bd ? __ldg(&bidx[j]) : __ldg(&iidx[j - NB]);
    const float* W1 = bd ? smem : smem + 1184;
    const float* b1 = bd ? smem + 96 : smem + 1248;
    const float* W2 = bd ? smem + 128 : smem + 1280;
    const float* b2 = bd ? smem + 1152 : smem + 2304;
    float2 xv = __ldg((const float2*)x + node);
    float yv = bd ? __ldg(&y[node]) : 0.0f;

    // Stage 1: h[32] = relu(MLP2(relu(MLP1(feats)))) — constant-indexed under
    // full unroll (register-resident; same pattern as earlier passing rounds).
    float h[32];
#pragma unroll
    for (int tile = 0; tile < 4; tile++) {
        float acc[8];
#pragma unroll
        for (int jj = 0; jj < 8; jj++) acc[jj] = b2[tile * 8 + jj];
#pragma unroll 8
        for (int k = 0; k < 32; k++) {
            float a = xv.x * W1[k] + xv.y * W1[32 + k] + b1[k];
            if (bd) a += yv * W1[64 + k];
            a = fmaxf(a, 0.0f);
            const float* wrow = W2 + k * 32 + tile * 8;
#pragma unroll
            for (int jj = 0; jj < 8; jj++) acc[jj] += a * wrow[jj];
        }
#pragma unroll
        for (int jj = 0; jj < 8; jj++) h[tile * 8 + jj] = fmaxf(acc[jj], 0.0f);
    }

    // Stage 2: t0 = (h @ Wc1) * dinv, fp16 (fully unrolled; constant indices)
    float di = g_dinv[node];
    const float* sWc = smem + 2336;
    unsigned* tp = (unsigned*)&g_t0[node * HH];
#pragma unroll
    for (int tile = 0; tile < 4; tile++) {
        float acc[8];
#pragma unroll
        for (int jj = 0; jj < 8; jj++) acc[jj] = 0.0f;
#pragma unroll
        for (int k = 0; k < 32; k++) {
            float v = h[k];
            const float* wrow = sWc + k * 32 + tile * 8;
#pragma unroll
            for (int jj = 0; jj < 8; jj++) acc[jj] += v * wrow[jj];
        }
        tp[tile * 4 + 0] = pk(acc[0] * di, acc[1] * di);
        tp[tile * 4 + 1] = pk(acc[2] * di, acc[3] * di);
        tp[tile * 4 + 2] = pk(acc[4] * di, acc[5] * di);
        tp[tile * 4 + 3] = pk(acc[6] * di, acc[7] * di);
    }
}

// ---------------------------------------------------------------------------
// Shared gather core: 4 lanes/node, lane sub owns 8 columns (uint4 row load).
// Returns relu(b + dinv * (self + sum_in)) for this lane's 8 columns, by value.
// ---------------------------------------------------------------------------
struct H8 { float4 a, b; };

__device__ __forceinline__ void addu4(float4& a, float4& b, uint4 u) {
    const __half2* hh = (const __half2*)&u;
    float2 f0 = __half22float2(hh[0]);
    float2 f1 = __half22float2(hh[1]);
    float2 f2 = __half22float2(hh[2]);
    float2 f3 = __half22float2(hh[3]);
    a.x += f0.x; a.y += f0.y; a.z += f1.x; a.w += f1.y;
    b.x += f2.x; b.y += f2.y; b.z += f3.x; b.w += f3.y;
}

__device__ __forceinline__ H8 gather_core(const __half* __restrict__ tin,
                                          const float* __restrict__ bvec,
                                          int node, int sub) {
    const uint4* tp = (const uint4*)tin;
    float4 aA0 = make_float4(0.f, 0.f, 0.f, 0.f), aA1 = aA0;
    float4 aB0 = aA0, aB1 = aA0;
    addu4(aA0, aA1, __ldg(tp + node * 4 + sub));        // self term
    int e = __ldg(&g_rowptr[node]);
    int e1 = __ldg(&g_rowptr[node + 1]);
    for (; e + 3 < e1; e += 4) {
        int s0 = __ldg(&g_csri[e + 0]);
        int s1 = __ldg(&g_csri[e + 1]);
        int s2 = __ldg(&g_csri[e + 2]);
        int s3 = __ldg(&g_csri[e + 3]);
        uint4 u0 = __ldg(tp + s0 * 4 + sub);
        uint4 u1 = __ldg(tp + s1 * 4 + sub);
        uint4 u2 = __ldg(tp + s2 * 4 + sub);
        uint4 u3 = __ldg(tp + s3 * 4 + sub);
        addu4(aA0, aA1, u0);
        addu4(aB0, aB1, u1);
        addu4(aA0, aA1, u2);
        addu4(aB0, aB1, u3);
    }
    for (; e < e1; e++)
        addu4(aA0, aA1, __ldg(tp + __ldg(&g_csri[e]) * 4 + sub));

    float di = g_dinv[node];
    const float4* bp = (const float4*)bvec;
    float4 b0 = __ldg(bp + sub * 2 + 0);
    float4 b1 = __ldg(bp + sub * 2 + 1);
    H8 h;
    h.a.x = fmaxf(b0.x + di * (aA0.x + aB0.x), 0.0f);
    h.a.y = fmaxf(b0.y + di * (aA0.y + aB0.y), 0.0f);
    h.a.z = fmaxf(b0.z + di * (aA0.z + aB0.z), 0.0f);
    h.a.w = fmaxf(b0.w + di * (aA0.w + aB0.w), 0.0f);
    h.b.x = fmaxf(b1.x + di * (aA1.x + aB1.x), 0.0f);
    h.b.y = fmaxf(b1.y + di * (aA1.y + aB1.y), 0.0f);
    h.b.z = fmaxf(b1.z + di * (aA1.z + aB1.z), 0.0f);
    h.b.w = fmaxf(b1.w + di * (aA1.w + aB1.w), 0.0f);
    return h;
}

// ---------------------------------------------------------------------------
// Gather + next-layer xform fused. Quad shuffles assemble the full 32-dim h,
// each lane computes its 8 columns of t_next = (h @ Wnext) * dinv.
// 8 named scalar accumulators; no indexed local arrays anywhere.
// ---------------------------------------------------------------------------
#define XSTEP(comp, ridx)                                                    \
    {                                                                        \
        float hv = __shfl_sync(0xFFFFFFFFu, (comp), q, 4);                   \
        const float* w = sW + (q * 8 + (ridx)) * 32 + sub * 8;               \
        a0 += hv * w[0]; a1 += hv * w[1]; a2 += hv * w[2]; a3 += hv * w[3];  \
        a4 += hv * w[4]; a5 += hv * w[5]; a6 += hv * w[6]; a7 += hv * w[7];  \
    }

__global__ void gx_kernel(int in_sel, int out_sel,
                          const float* __restrict__ bvec, const float* __restrict__ Wnext) {
    __shared__ float sW[1024];
    for (int i = threadIdx.x; i < 1024; i += blockDim.x) sW[i] = Wnext[i];
    __syncthreads();

    const __half* tin = tbuf(in_sel);
    __half* tout = tbuf(out_sel);

    int gid = blockIdx.x * blockDim.x + threadIdx.x;
    int node = gid >> 2, sub = gid & 3;
    if (node >= NN) node = NN - 1;          // clamp; duplicate quads write same data

    H8 h = gather_core(tin, bvec, node, sub);

    float di = g_dinv[node];
    float a0 = 0.f, a1 = 0.f, a2 = 0.f, a3 = 0.f;
    float a4 = 0.f, a5 = 0.f, a6 = 0.f, a7 = 0.f;
#pragma unroll
    for (int q = 0; q < 4; q++) {
        XSTEP(h.a.x, 0) XSTEP(h.a.y, 1) XSTEP(h.a.z, 2) XSTEP(h.a.w, 3)
        XSTEP(h.b.x, 4) XSTEP(h.b.y, 5) XSTEP(h.b.z, 6) XSTEP(h.b.w, 7)
    }
    uint4 o;
    o.x = pk(a0 * di, a1 * di);
    o.y = pk(a2 * di, a3 * di);
    o.z = pk(a4 * di, a5 * di);
    o.w = pk(a6 * di, a7 * di);
    ((uint4*)tout)[node * 4 + sub] = o;
}

// ---------------------------------------------------------------------------
// Last gather + head fused: out[node] = dot(relu(h3), Wf) + bf via quad reduce.
// ---------------------------------------------------------------------------
__global__ void ghead_kernel(int in_sel, const float* __restrict__ bvec,
                             const float* __restrict__ Wf, const float* __restrict__ bf,
                             float* __restrict__ out) {
    const __half* tin = tbuf(in_sel);
    int gid = blockIdx.x * blockDim.x + threadIdx.x;
    int node = gid >> 2, sub = gid & 3;
    if (node >= NN) node = NN - 1;

    H8 h = gather_core(tin, bvec, node, sub);

    const float4* wp = (const float4*)Wf;
    float4 w0 = __ldg(wp + sub * 2 + 0);
    float4 w1 = __ldg(wp + sub * 2 + 1);
    float p = h.a.x * w0.x + h.a.y * w0.y + h.a.z * w0.z + h.a.w * w0.w +
              h.b.x * w1.x + h.b.y * w1.y + h.b.z * w1.z + h.b.w * w1.w;
    p += __shfl_xor_sync(0xFFFFFFFFu, p, 1, 4);
    p += __shfl_xor_sync(0xFFFFFFFFu, p, 2, 4);
    if (sub == 0) out[node] = p + __ldg(bf);
}

extern "C" void kernel_launch(void* const* d_in, const int* in_sizes, int n_in,
                              void* d_out, int out_size) {
    const float* x    = (const float*)d_in[0];
    const float* y    = (const float*)d_in[1];
    const int*   ei   = (const int*)d_in[2];
    const int*   bidx = (const int*)d_in[3];
    const int*   iidx = (const int*)d_in[4];
    const float* Wb1 = (const float*)d_in[5];
    const float* bb1 = (const float*)d_in[6];
    const float* Wb2 = (const float*)d_in[7];
    const float* bb2 = (const float*)d_in[8];
    const float* Wi1 = (const float*)d_in[9];
    const float* bi1 = (const float*)d_in[10];
    const float* Wi2 = (const float*)d_in[11];
    const float* bi2 = (const float*)d_in[12];
    const float* Wc1 = (const float*)d_in[13];
    const float* bc1 = (const float*)d_in[14];
    const float* Wc2 = (const float*)d_in[15];
    const float* bc2 = (const float*)d_in[16];
    const float* Wc3 = (const float*)d_in[17];
    const float* bc3 = (const float*)d_in[18];
    const float* Wf  = (const float*)d_in[19];
    const float* bf  = (const float*)d_in[20];

    int NB = in_sizes[3];
    const int* src = ei;        // edge_index[0,:]
    const int* dst = ei + EE;   // edge_index[1,:]

    // CSR pipeline
    deg_kernel<<<CDIV(EE / 4, 256), 256>>>(dst);               // 1
    scan1_kernel<<<NTILE, 256>>>();                            // 2 (dinv + tile scan)
    scan3_kernel<<<CDIV(NN, 256), 256>>>();                    // 3
    fill_kernel<<<CDIV(EE / 4, 256), 256>>>(src, dst);         // 4  <- profiled slot

    // Encoder + xform1 -> t0
    enc_x1_kernel<<<CDIV(NN, 128), 128>>>(x, y, bidx, iidx, NB,
                                          Wb1, bb1, Wb2, bb2, Wi1, bi1, Wi2, bi2,
                                          Wc1);                // 5

    // Conv1 gather + xform2 -> t1 ; Conv2 gather + xform3 -> t0 ; Conv3 gather + head
    gx_kernel<<<CDIV(NN * 4, 256), 256>>>(0, 1, bc1, Wc2);     // 6
    gx_kernel<<<CDIV(NN * 4, 256), 256>>>(1, 0, bc2, Wc3);     // 7
    ghead_kernel<<<CDIV(NN * 4, 256), 256>>>(0, bc3, Wf, bf,
                                             (float*)d_out);   // 8
}